// round 1
// baseline (speedup 1.0000x reference)
#include <cuda_runtime.h>
#include <cstdint>

#define Bn 32
#define Fn 64
#define Ln 8192
#define Pn 96
#define Hn 8

// ---------------- scratch (device globals: no allocation allowed) ----------------
__device__ float g_mean[Bn * Fn];
__device__ float g_istd[Bn * Fn];   // 1/(std+eps)
__device__ float g_stdp[Bn * Fn];   // std+eps
__device__ float g_KV[Bn * Hn * 64];
__device__ float g_Z[Bn * Hn * 8];
__device__ float g_M[Bn * Pn * Fn];
__device__ float g_y[(size_t)Bn * Fn * Ln];   // 64 MB, layout [b][f][l]

// ---------------- helpers ----------------
__device__ __forceinline__ float phi_fn(float v) {
    // elu(x)+1 : x>0 ? x+1 : exp(x)
    return v > 0.f ? v + 1.f : __expf(v);
}

__device__ __forceinline__ float wsum(float p) {
    p += __shfl_xor_sync(0xffffffffu, p, 16);
    p += __shfl_xor_sync(0xffffffffu, p, 8);
    p += __shfl_xor_sync(0xffffffffu, p, 4);
    p += __shfl_xor_sync(0xffffffffu, p, 2);
    p += __shfl_xor_sync(0xffffffffu, p, 1);
    return p;
}

__device__ __forceinline__ float dot64(const float xn[64], const float4* __restrict__ w) {
    float a0 = 0.f, a1 = 0.f, a2 = 0.f, a3 = 0.f;
#pragma unroll
    for (int i = 0; i < 16; i++) {
        float4 q = w[i];
        a0 = fmaf(xn[4 * i + 0], q.x, a0);
        a1 = fmaf(xn[4 * i + 1], q.y, a1);
        a2 = fmaf(xn[4 * i + 2], q.z, a2);
        a3 = fmaf(xn[4 * i + 3], q.w, a3);
    }
    return (a0 + a1) + (a2 + a3);
}

// ---------------- kernel 0: zero the accumulators ----------------
__global__ void k_zero() {
    int i = blockIdx.x * blockDim.x + threadIdx.x;
    if (i < Bn * Hn * 64) g_KV[i] = 0.f;
    if (i < Bn * Hn * 8)  g_Z[i]  = 0.f;
    if (i < Bn * Pn * Fn) g_M[i]  = 0.f;
}

// ---------------- kernel 1: RevIN stats per (b,f) ----------------
__global__ __launch_bounds__(256) void k_stats(const float* __restrict__ x) {
    int bf = blockIdx.x;
    const float* p = x + (size_t)bf * Ln;
    float s1 = 0.f, s2 = 0.f;
    for (int i = threadIdx.x; i < Ln; i += 256) {
        float v = p[i];
        s1 += v;
        s2 = fmaf(v, v, s2);
    }
    __shared__ float r1[256], r2[256];
    r1[threadIdx.x] = s1; r2[threadIdx.x] = s2;
    __syncthreads();
    for (int s = 128; s > 0; s >>= 1) {
        if (threadIdx.x < s) {
            r1[threadIdx.x] += r1[threadIdx.x + s];
            r2[threadIdx.x] += r2[threadIdx.x + s];
        }
        __syncthreads();
    }
    if (threadIdx.x == 0) {
        float S1 = r1[0], S2 = r2[0];
        float mean = S1 / (float)Ln;
        float var  = (S2 - S1 * mean) / (float)(Ln - 1);  // ddof=1
        var = fmaxf(var, 0.f);
        float stdp = sqrtf(var) + 1e-5f;                   // EPS_REVIN
        g_mean[bf] = mean;
        g_stdp[bf] = stdp;
        g_istd[bf] = 1.f / stdp;
    }
}

// ---------------- kernel 2: K/V projections + KV,Z accumulation ----------------
__global__ __launch_bounds__(256, 2) void k_kv(
    const float* __restrict__ x, const float* __restrict__ gamma, const float* __restrict__ beta,
    const float* __restrict__ lnw, const float* __restrict__ lnb,
    const float* __restrict__ Wk, const float* __restrict__ bk,
    const float* __restrict__ Wv, const float* __restrict__ bv)
{
    __shared__ float4 Wk4[Fn * 16], Wv4[Fn * 16];
    __shared__ float dks[64], cks[64], dvs[64], cvs[64], As[64], Cs[64];
    int b = blockIdx.y;
    int tid = threadIdx.x;
    int lane = tid & 31;

    float* Wkf = (float*)Wk4;
    float* Wvf = (float*)Wv4;
#pragma unroll
    for (int i = 0; i < 16; i++) {
        int idx = tid + i * 256;
        int f = idx & 63;
        float lw = lnw[f];
        Wkf[idx] = Wk[idx] * lw;   // fold LN weight into projection
        Wvf[idx] = Wv[idx] * lw;
    }
    if (tid < 64) {
        As[tid] = gamma[tid] * g_istd[b * 64 + tid];
        Cs[tid] = beta[tid] - g_mean[b * 64 + tid] * As[tid];
    }
    __syncthreads();
    if (tid < 64) {
        float d = 0.f, c = 0.f;
#pragma unroll
        for (int f = 0; f < 64; f++) {
            d += Wkf[tid * 64 + f];
            c = fmaf(lnb[f], Wk[tid * 64 + f], c);
        }
        dks[tid] = d;
        cks[tid] = c + bk[tid];
    } else if (tid < 128) {
        int e = tid - 64;
        float d = 0.f, c = 0.f;
#pragma unroll
        for (int f = 0; f < 64; f++) {
            d += Wvf[e * 64 + f];
            c = fmaf(lnb[f], Wv[e * 64 + f], c);
        }
        dvs[e] = d;
        cvs[e] = c + bv[e];
    }
    __syncthreads();

    int l = blockIdx.x * 256 + tid;
    float xn[64];
    float s1 = 0.f, s2 = 0.f;
#pragma unroll
    for (int f = 0; f < 64; f++) {
        float v = x[((size_t)(b * 64 + f)) * Ln + l];
        float t = fmaf(v, As[f], Cs[f]);
        xn[f] = t;
        s1 += t;
        s2 = fmaf(t, t, s2);
    }
    float mu = s1 * (1.f / 64.f);
    float rs = rsqrtf(fmaf(-mu, mu, s2 * (1.f / 64.f)) + 1e-5f);   // EPS_LN

    for (int hh = 0; hh < 8; hh++) {
        float kk[8], vv[8];
#pragma unroll
        for (int j = 0; j < 8; j++) {
            int e = hh * 8 + j;
            float Sk = dot64(xn, Wk4 + e * 16);
            float kp = fmaf(rs, Sk - mu * dks[e], cks[e]);
            kk[j] = phi_fn(kp);
            float Sv = dot64(xn, Wv4 + e * 16);
            vv[j] = fmaf(rs, Sv - mu * dvs[e], cvs[e]);
        }
        float zown = 0.f, a0 = 0.f, a1 = 0.f;
#pragma unroll
        for (int d = 0; d < 8; d++) {
            float z = wsum(kk[d]);
            if (lane == d) zown = z;
#pragma unroll
            for (int e2 = 0; e2 < 8; e2++) {
                float pr = wsum(kk[d] * vv[e2]);
                int idx = d * 8 + e2;
                if (idx < 32) { if (lane == idx) a0 = pr; }
                else          { if (lane == idx - 32) a1 = pr; }
            }
        }
        float* kvb = &g_KV[(b * 8 + hh) * 64];
        atomicAdd(kvb + lane, a0);
        atomicAdd(kvb + 32 + lane, a1);
        if (lane < 8) atomicAdd(&g_Z[(b * 8 + hh) * 8 + lane], zown);
    }
}

// ---------------- kernel 3: Q projection, attention, Wo + residual -> y ----------------
__global__ __launch_bounds__(256, 1) void k_qo(
    const float* __restrict__ x, const float* __restrict__ gamma, const float* __restrict__ beta,
    const float* __restrict__ lnw, const float* __restrict__ lnb,
    const float* __restrict__ Wq, const float* __restrict__ bq,
    const float* __restrict__ Wo, const float* __restrict__ bo)
{
    __shared__ float4 Wq4[Fn * 16], Wo4[Fn * 16];   // Wo4 holds Wo^T
    __shared__ float dqs[64], cqs[64], As[64], Cs[64], bos[64];
    __shared__ float KVs[8 * 64];
    __shared__ float Zs[64];
    int b = blockIdx.y, tid = threadIdx.x;

    float* Wqf = (float*)Wq4;
    float* Wof = (float*)Wo4;
#pragma unroll
    for (int i = 0; i < 16; i++) {
        int idx = tid + i * 256;
        int e = idx >> 6, f = idx & 63;
        Wqf[idx] = Wq[idx] * lnw[f];
        Wof[idx] = Wo[f * 64 + e];      // transpose: WoT[e][f] = Wo[f][e]
    }
    if (tid < 64) {
        As[tid]  = gamma[tid] * g_istd[b * 64 + tid];
        Cs[tid]  = beta[tid] - g_mean[b * 64 + tid] * As[tid];
        bos[tid] = bo[tid];
        Zs[tid]  = g_Z[b * 64 + tid];
    }
    KVs[tid]       = g_KV[b * 512 + tid];
    KVs[tid + 256] = g_KV[b * 512 + 256 + tid];
    __syncthreads();
    if (tid < 64) {
        float d = 0.f, c = 0.f;
#pragma unroll
        for (int f = 0; f < 64; f++) {
            d += Wqf[tid * 64 + f];
            c = fmaf(lnb[f], Wq[tid * 64 + f], c);
        }
        dqs[tid] = d;
        cqs[tid] = c + bq[tid];
    }
    __syncthreads();

    int l = blockIdx.x * 256 + tid;
    float xn[64];
    float s1 = 0.f, s2 = 0.f;
#pragma unroll
    for (int f = 0; f < 64; f++) {
        float v = x[((size_t)(b * 64 + f)) * Ln + l];
        float t = fmaf(v, As[f], Cs[f]);
        xn[f] = t;
        s1 += t;
        s2 = fmaf(t, t, s2);
    }
    float mu = s1 * (1.f / 64.f);
    float rs = rsqrtf(fmaf(-mu, mu, s2 * (1.f / 64.f)) + 1e-5f);

    float out[64];
#pragma unroll
    for (int f = 0; f < 64; f++) out[f] = xn[f] + bos[f];   // residual + bo

    for (int hh = 0; hh < 8; hh++) {
        float q[8];
#pragma unroll
        for (int j = 0; j < 8; j++) {
            int e = hh * 8 + j;
            float S = dot64(xn, Wq4 + e * 16);
            float qp = fmaf(rs, S - mu * dqs[e], cqs[e]);
            q[j] = phi_fn(qp);
        }
        float nrm = 1e-6f;   // EPS_ATTN
#pragma unroll
        for (int d = 0; d < 8; d++) nrm = fmaf(q[d], Zs[hh * 8 + d], nrm);
        float inv = 1.f / nrm;
#pragma unroll
        for (int j = 0; j < 8; j++) {
            float s = 0.f;
#pragma unroll
            for (int d = 0; d < 8; d++) s = fmaf(q[d], KVs[hh * 64 + d * 8 + j], s);
            float a = s * inv;
            const float4* wrow = Wo4 + (hh * 8 + j) * 16;
#pragma unroll
            for (int i = 0; i < 16; i++) {
                float4 w = wrow[i];
                out[4 * i + 0] = fmaf(a, w.x, out[4 * i + 0]);
                out[4 * i + 1] = fmaf(a, w.y, out[4 * i + 1]);
                out[4 * i + 2] = fmaf(a, w.z, out[4 * i + 2]);
                out[4 * i + 3] = fmaf(a, w.w, out[4 * i + 3]);
            }
        }
    }
#pragma unroll
    for (int f = 0; f < 64; f++)
        g_y[((size_t)(b * 64 + f)) * Ln + l] = out[f];
}

// ---------------- kernel 4: temporal GEMM M[b,p,f] = sum_l Wlin[p,l] * y[b,f,l] ----------------
__global__ __launch_bounds__(256, 4) void k_gemm(const float* __restrict__ Wlin) {
    __shared__ float wls[96][33];
    __shared__ float ys[64][33];
    int b = blockIdx.y;
    int l0 = blockIdx.x * 512;
    int tid = threadIdx.x;
    int tp = tid & 31, tf = tid >> 5;

    float acc[3][8];
#pragma unroll
    for (int i = 0; i < 3; i++)
#pragma unroll
        for (int k = 0; k < 8; k++) acc[i][k] = 0.f;

    for (int t = 0; t < 16; t++) {
        int lb = l0 + t * 32;
#pragma unroll
        for (int i = 0; i < 12; i++) {
            int e = tid + i * 256;
            wls[e >> 5][e & 31] = Wlin[(size_t)(e >> 5) * Ln + lb + (e & 31)];
        }
#pragma unroll
        for (int i = 0; i < 8; i++) {
            int f = tf + i * 8;
            ys[f][tp] = g_y[((size_t)(b * 64 + f)) * Ln + lb + tp];
        }
        __syncthreads();
#pragma unroll
        for (int j = 0; j < 32; j++) {
            float w0 = wls[tp][j], w1 = wls[tp + 32][j], w2 = wls[tp + 64][j];
#pragma unroll
            for (int k = 0; k < 8; k++) {
                float yv = ys[tf * 8 + k][j];
                acc[0][k] = fmaf(w0, yv, acc[0][k]);
                acc[1][k] = fmaf(w1, yv, acc[1][k]);
                acc[2][k] = fmaf(w2, yv, acc[2][k]);
            }
        }
        __syncthreads();
    }
#pragma unroll
    for (int i = 0; i < 3; i++)
#pragma unroll
        for (int k = 0; k < 8; k++)
            atomicAdd(&g_M[(b * 96 + tp + 32 * i) * 64 + tf * 8 + k], acc[i][k]);
}

// ---------------- kernel 5: denorm + projector ----------------
__global__ void k_epi(const float* __restrict__ gamma, const float* __restrict__ beta,
                      const float* __restrict__ blin, const float* __restrict__ Wp,
                      const float* __restrict__ bp, float* __restrict__ out) {
    int b = blockIdx.x, p = threadIdx.x;
    float bl = blin[p];
    float s = bp[0];
#pragma unroll
    for (int f = 0; f < 64; f++) {
        float y = g_M[(b * 96 + p) * 64 + f] + bl;
        y = (y - beta[f]) / gamma[f];
        y = fmaf(y, g_stdp[b * 64 + f], g_mean[b * 64 + f]);
        s = fmaf(y, Wp[f], s);
    }
    out[b * 96 + p] = s;
}

// ---------------- launch ----------------
extern "C" void kernel_launch(void* const* d_in, const int* in_sizes, int n_in,
                              void* d_out, int out_size) {
    (void)in_sizes; (void)n_in; (void)out_size;
    const float* x     = (const float*)d_in[0];
    const float* gamma = (const float*)d_in[1];
    const float* beta  = (const float*)d_in[2];
    const float* lnw   = (const float*)d_in[3];
    const float* lnb   = (const float*)d_in[4];
    const float* Wq    = (const float*)d_in[5];
    const float* bq    = (const float*)d_in[6];
    const float* Wk    = (const float*)d_in[7];
    const float* bk    = (const float*)d_in[8];
    const float* Wv    = (const float*)d_in[9];
    const float* bv    = (const float*)d_in[10];
    const float* Wo    = (const float*)d_in[11];
    const float* bo    = (const float*)d_in[12];
    const float* Wlin  = (const float*)d_in[13];
    const float* blin  = (const float*)d_in[14];
    const float* Wp    = (const float*)d_in[15];
    const float* bp    = (const float*)d_in[16];
    float* out = (float*)d_out;

    k_zero<<<768, 256>>>();
    k_stats<<<Bn * Fn, 256>>>(x);
    k_kv<<<dim3(Ln / 256, Bn), 256>>>(x, gamma, beta, lnw, lnb, Wk, bk, Wv, bv);
    k_qo<<<dim3(Ln / 256, Bn), 256>>>(x, gamma, beta, lnw, lnb, Wq, bq, Wo, bo);
    k_gemm<<<dim3(Ln / 512, Bn), 256>>>(Wlin);
    k_epi<<<Bn, Pn>>>(gamma, beta, blin, Wp, bp, out);
}

// round 2
// speedup vs baseline: 1.1786x; 1.1786x over previous
#include <cuda_runtime.h>
#include <cstdint>

#define Bn 32
#define Fn 64
#define Ln 8192
#define Pn 96
#define SR 132   // shared tile row stride (floats): conflict-free rows & columns

typedef unsigned long long ull;

// ---------------- scratch (device globals) ----------------
__device__ float g_mean[Bn * Fn];
__device__ float g_istd[Bn * Fn];
__device__ float g_stdp[Bn * Fn];
__device__ float g_KV[Bn * 512];
__device__ float g_Z[Bn * 64];
__device__ float g_M[Bn * Pn * Fn];
__device__ float g_y[(size_t)Bn * Fn * Ln];
// pre-folded, duplicated (f32x2) weights: layout [k(=input dim)][e(=output dim)]
__device__ float2 g_Wqp[4096], g_Wkp[4096], g_Wvp[4096], g_Wop[4096];
__device__ float g_dq[64], g_cq[64], g_dk[64], g_ck[64], g_dv[64], g_cv[64];

// ---------------- helpers ----------------
__device__ __forceinline__ void fma2(ull& d, ull a, ull b) {
    asm("fma.rn.f32x2 %0, %1, %2, %0;" : "+l"(d) : "l"(a), "l"(b));
}
__device__ __forceinline__ float2 upk(ull v) {
    float2 r;
    asm("mov.b64 {%0, %1}, %2;" : "=f"(r.x), "=f"(r.y) : "l"(v));
    return r;
}
__device__ __forceinline__ float phi_fn(float v) {
    return v > 0.f ? v + 1.f : __expf(v);   // elu(x)+1
}

// 64-deep GEMM micro-tile: 4 outputs (e) x 8 positions (l as 4 f32x2 pairs)
__device__ __forceinline__ void gemm_tile(const float* __restrict__ hb,
                                          const ull* __restrict__ wbase,
                                          ull acc[4][4]) {
#pragma unroll
    for (int i = 0; i < 4; i++) { acc[i][0] = 0ULL; acc[i][1] = 0ULL; acc[i][2] = 0ULL; acc[i][3] = 0ULL; }
#pragma unroll 4
    for (int k = 0; k < 64; k++) {
        ulonglong2 h01 = *(const ulonglong2*)(hb + k * SR);
        ulonglong2 h23 = *(const ulonglong2*)(hb + k * SR + 4);
        const ull* wr = wbase + k * 64;
#pragma unroll
        for (int i = 0; i < 4; i++) {
            ull w = wr[i];
            fma2(acc[i][0], w, h01.x);
            fma2(acc[i][1], w, h01.y);
            fma2(acc[i][2], w, h23.x);
            fma2(acc[i][3], w, h23.y);
        }
    }
}

// ---------------- kernel 0: zero accumulators ----------------
__global__ void k_zero() {
    int i = blockIdx.x * blockDim.x + threadIdx.x;
    if (i < Bn * 512)      g_KV[i] = 0.f;
    if (i < Bn * 64)       g_Z[i]  = 0.f;
    if (i < Bn * Pn * Fn)  g_M[i]  = 0.f;
}

// ---------------- kernel prep: fold LN into weights, duplicate pairs ----------------
__global__ void __launch_bounds__(256) k_prep(
    const float* __restrict__ lnw, const float* __restrict__ lnb,
    const float* __restrict__ Wq, const float* __restrict__ bq,
    const float* __restrict__ Wk, const float* __restrict__ bk,
    const float* __restrict__ Wv, const float* __restrict__ bv,
    const float* __restrict__ Wo)
{
    int tid = threadIdx.x;
#pragma unroll
    for (int i = 0; i < 16; i++) {
        int idx = tid + i * 256;          // idx = f*64 + e
        int f = idx >> 6, e = idx & 63;
        float lw = lnw[f];
        float wq = Wq[e * 64 + f] * lw;  g_Wqp[idx] = make_float2(wq, wq);
        float wk = Wk[e * 64 + f] * lw;  g_Wkp[idx] = make_float2(wk, wk);
        float wv = Wv[e * 64 + f] * lw;  g_Wvp[idx] = make_float2(wv, wv);
        // Wo transposed: wbuf[k=e_att][fo] = Wo[fo][e_att]; here row=f plays e_att, col=e plays fo
        float wo = Wo[e * 64 + f];       g_Wop[idx] = make_float2(wo, wo);
    }
    if (tid < 64) {
        int e = tid;
        float dq = 0.f, cq = 0.f, dk = 0.f, ck = 0.f, dv = 0.f, cv = 0.f;
        for (int f = 0; f < 64; f++) {
            float lw = lnw[f], lb2 = lnb[f];
            float wq = Wq[e * 64 + f], wk = Wk[e * 64 + f], wv = Wv[e * 64 + f];
            dq += wq * lw;  cq = fmaf(lb2, wq, cq);
            dk += wk * lw;  ck = fmaf(lb2, wk, ck);
            dv += wv * lw;  cv = fmaf(lb2, wv, cv);
        }
        g_dq[e] = dq; g_cq[e] = cq + bq[e];
        g_dk[e] = dk; g_ck[e] = ck + bk[e];
        g_dv[e] = dv; g_cv[e] = cv + bv[e];
    }
}

// ---------------- kernel 1: RevIN stats per (b,f) ----------------
__global__ void __launch_bounds__(256) k_stats(const float* __restrict__ x) {
    int bf = blockIdx.x;
    const float4* p = (const float4*)(x + (size_t)bf * Ln);
    float s1 = 0.f, s2 = 0.f;
    for (int i = threadIdx.x; i < Ln / 4; i += 256) {
        float4 v = p[i];
        s1 += (v.x + v.y) + (v.z + v.w);
        s2 = fmaf(v.x, v.x, s2); s2 = fmaf(v.y, v.y, s2);
        s2 = fmaf(v.z, v.z, s2); s2 = fmaf(v.w, v.w, s2);
    }
    __shared__ float r1[256], r2[256];
    r1[threadIdx.x] = s1; r2[threadIdx.x] = s2;
    __syncthreads();
    for (int s = 128; s > 0; s >>= 1) {
        if (threadIdx.x < s) {
            r1[threadIdx.x] += r1[threadIdx.x + s];
            r2[threadIdx.x] += r2[threadIdx.x + s];
        }
        __syncthreads();
    }
    if (threadIdx.x == 0) {
        float S1 = r1[0], S2 = r2[0];
        float mean = S1 / (float)Ln;
        float var = (S2 - S1 * mean) / (float)(Ln - 1);
        var = fmaxf(var, 0.f);
        float stdp = sqrtf(var) + 1e-5f;
        g_mean[bf] = mean; g_stdp[bf] = stdp; g_istd[bf] = 1.f / stdp;
    }
}

// ---------------- kernel 2: K/V projections + KV,Z (tiled GEMM, f32x2) ----------------
__global__ void __launch_bounds__(256, 2) k_kv(
    const float* __restrict__ x, const float* __restrict__ gamma, const float* __restrict__ beta)
{
    extern __shared__ float sm[];
    float*  xns = sm;                          // 64*SR floats; later reused as kb
    float*  vb  = sm + 64 * SR;                // 64*SR
    float2* wb  = (float2*)(sm + 2 * 64 * SR); // 4096 float2
    __shared__ float mus[128], rss[128], As[64], Cs[64];
    __shared__ float dks[64], cks[64], dvs[64], cvs[64];

    int b = blockIdx.y, tid = threadIdx.x;
    int l0b = blockIdx.x * 128;

    if (tid < 64) {
        float a = gamma[tid] * g_istd[b * 64 + tid];
        As[tid] = a;
        Cs[tid] = beta[tid] - g_mean[b * 64 + tid] * a;
        dks[tid] = g_dk[tid]; cks[tid] = g_ck[tid];
        dvs[tid] = g_dv[tid]; cvs[tid] = g_cv[tid];
    }
    {   // wb <- Wv packed
        const float4* src = (const float4*)g_Wvp;
        float4* dst = (float4*)wb;
#pragma unroll
        for (int i = 0; i < 8; i++) dst[tid + i * 256] = src[tid + i * 256];
    }
    __syncthreads();
    // xn tile
#pragma unroll
    for (int i = 0; i < 8; i++) {
        int idx = tid + i * 256;
        int f = idx >> 5, c = idx & 31;
        float4 v = *(const float4*)(x + ((size_t)(b * 64 + f)) * Ln + l0b + c * 4);
        float a = As[f], c0 = Cs[f];
        v.x = fmaf(v.x, a, c0); v.y = fmaf(v.y, a, c0);
        v.z = fmaf(v.z, a, c0); v.w = fmaf(v.w, a, c0);
        *(float4*)(xns + f * SR + c * 4) = v;
    }
    __syncthreads();
    if (tid < 128) {
        float s1 = 0.f, s2 = 0.f;
#pragma unroll
        for (int f = 0; f < 64; f++) { float t = xns[f * SR + tid]; s1 += t; s2 = fmaf(t, t, s2); }
        float mu = s1 * (1.f / 64.f);
        mus[tid] = mu;
        rss[tid] = rsqrtf(fmaf(-mu, mu, s2 * (1.f / 64.f)) + 1e-5f);
    }
    __syncthreads();

    int lg = tid & 15, eg = tid >> 4;
    int l0 = lg * 8, e0 = eg * 4;
    const float* hb = xns + l0;
    const ull* wbase = (const ull*)wb + e0;
    ull acc[4][4];

    // ---- V GEMM ----
    gemm_tile(hb, wbase, acc);
#pragma unroll
    for (int i = 0; i < 4; i++) {
        int e = e0 + i; float dv = dvs[e], cv = cvs[e];
#pragma unroll
        for (int p = 0; p < 4; p++) {
            float2 s = upk(acc[i][p]);
            int l = l0 + 2 * p;
            vb[e * SR + l]     = fmaf(rss[l],     s.x - mus[l] * dv,     cv);
            vb[e * SR + l + 1] = fmaf(rss[l + 1], s.y - mus[l + 1] * dv, cv);
        }
    }
    __syncthreads();
    {   // wb <- Wk packed
        const float4* src = (const float4*)g_Wkp;
        float4* dst = (float4*)wb;
#pragma unroll
        for (int i = 0; i < 8; i++) dst[tid + i * 256] = src[tid + i * 256];
    }
    __syncthreads();

    // ---- K GEMM (phi into regs, then overwrite xns as kb) ----
    gemm_tile(hb, wbase, acc);
    float kreg[32];
#pragma unroll
    for (int i = 0; i < 4; i++) {
        int e = e0 + i; float dk = dks[e], ck = cks[e];
#pragma unroll
        for (int p = 0; p < 4; p++) {
            float2 s = upk(acc[i][p]);
            int l = l0 + 2 * p;
            kreg[i * 8 + 2 * p]     = phi_fn(fmaf(rss[l],     s.x - mus[l] * dk,     ck));
            kreg[i * 8 + 2 * p + 1] = phi_fn(fmaf(rss[l + 1], s.y - mus[l + 1] * dk, ck));
        }
    }
    __syncthreads();
#pragma unroll
    for (int i = 0; i < 4; i++)
#pragma unroll
        for (int p = 0; p < 8; p++)
            xns[(e0 + i) * SR + l0 + p] = kreg[i * 8 + p];
    __syncthreads();

    // ---- KV / Z accumulation ----
    if (tid < 128) {
        int hh = tid >> 4;
        int sub = tid & 15;
        int d0 = (sub >> 2) << 1;   // 0,2,4,6
        int e2 = (sub & 3) << 1;    // 0,2,4,6
        const float* kr0 = xns + (hh * 8 + d0) * SR;
        const float* kr1 = kr0 + SR;
        const float* vr0 = vb + (hh * 8 + e2) * SR;
        const float* vr1 = vr0 + SR;
        ull a00 = 0, a01 = 0, a10 = 0, a11 = 0;
#pragma unroll 4
        for (int j = 0; j < 128; j += 4) {
            ulonglong2 kk0 = *(const ulonglong2*)(kr0 + j);
            ulonglong2 kk1 = *(const ulonglong2*)(kr1 + j);
            ulonglong2 vv0 = *(const ulonglong2*)(vr0 + j);
            ulonglong2 vv1 = *(const ulonglong2*)(vr1 + j);
            fma2(a00, kk0.x, vv0.x); fma2(a00, kk0.y, vv0.y);
            fma2(a01, kk0.x, vv1.x); fma2(a01, kk0.y, vv1.y);
            fma2(a10, kk1.x, vv0.x); fma2(a10, kk1.y, vv0.y);
            fma2(a11, kk1.x, vv1.x); fma2(a11, kk1.y, vv1.y);
        }
        float* kvb = &g_KV[(b * 8 + hh) * 64];
        float2 t;
        t = upk(a00); atomicAdd(kvb + d0 * 8 + e2,           t.x + t.y);
        t = upk(a01); atomicAdd(kvb + d0 * 8 + e2 + 1,       t.x + t.y);
        t = upk(a10); atomicAdd(kvb + (d0 + 1) * 8 + e2,     t.x + t.y);
        t = upk(a11); atomicAdd(kvb + (d0 + 1) * 8 + e2 + 1, t.x + t.y);
    } else if (tid < 192) {
        int r = tid - 128;
        const float* kr = xns + r * SR;
        float s = 0.f;
#pragma unroll
        for (int j = 0; j < 128; j += 4) {
            float4 v = *(const float4*)(kr + j);
            s += (v.x + v.y) + (v.z + v.w);
        }
        atomicAdd(&g_Z[b * 64 + r], s);
    }
}

// ---------------- kernel 3: Q projection, attention, Wo + residual -> y ----------------
__global__ void __launch_bounds__(256, 2) k_qo(
    const float* __restrict__ x, const float* __restrict__ gamma, const float* __restrict__ beta,
    const float* __restrict__ bo)
{
    extern __shared__ float sm[];
    float*  xns = sm;
    float*  qb  = sm + 64 * SR;
    float2* wb  = (float2*)(sm + 2 * 64 * SR);
    __shared__ float mus[128], rss[128], As[64], Cs[64], dqs[64], cqs[64], bos[64];
    __shared__ float KVs[512], Zs[64];

    int b = blockIdx.y, tid = threadIdx.x;
    int l0b = blockIdx.x * 128;

    if (tid < 64) {
        float a = gamma[tid] * g_istd[b * 64 + tid];
        As[tid] = a;
        Cs[tid] = beta[tid] - g_mean[b * 64 + tid] * a;
        dqs[tid] = g_dq[tid]; cqs[tid] = g_cq[tid];
        bos[tid] = bo[tid];
        Zs[tid] = g_Z[b * 64 + tid];
    }
    KVs[tid] = g_KV[b * 512 + tid];
    KVs[tid + 256] = g_KV[b * 512 + 256 + tid];
    {   // wb <- Wq packed
        const float4* src = (const float4*)g_Wqp;
        float4* dst = (float4*)wb;
#pragma unroll
        for (int i = 0; i < 8; i++) dst[tid + i * 256] = src[tid + i * 256];
    }
    __syncthreads();
#pragma unroll
    for (int i = 0; i < 8; i++) {
        int idx = tid + i * 256;
        int f = idx >> 5, c = idx & 31;
        float4 v = *(const float4*)(x + ((size_t)(b * 64 + f)) * Ln + l0b + c * 4);
        float a = As[f], c0 = Cs[f];
        v.x = fmaf(v.x, a, c0); v.y = fmaf(v.y, a, c0);
        v.z = fmaf(v.z, a, c0); v.w = fmaf(v.w, a, c0);
        *(float4*)(xns + f * SR + c * 4) = v;
    }
    __syncthreads();
    if (tid < 128) {
        float s1 = 0.f, s2 = 0.f;
#pragma unroll
        for (int f = 0; f < 64; f++) { float t = xns[f * SR + tid]; s1 += t; s2 = fmaf(t, t, s2); }
        float mu = s1 * (1.f / 64.f);
        mus[tid] = mu;
        rss[tid] = rsqrtf(fmaf(-mu, mu, s2 * (1.f / 64.f)) + 1e-5f);
    }
    __syncthreads();

    int lg = tid & 15, eg = tid >> 4;
    int l0 = lg * 8, e0 = eg * 4;
    const float* hb = xns + l0;
    const ull* wbase = (const ull*)wb + e0;
    ull acc[4][4];

    // ---- Q GEMM -> phi -> qb ----
    gemm_tile(hb, wbase, acc);
#pragma unroll
    for (int i = 0; i < 4; i++) {
        int e = e0 + i; float dq = dqs[e], cq = cqs[e];
#pragma unroll
        for (int p = 0; p < 4; p++) {
            float2 s = upk(acc[i][p]);
            int l = l0 + 2 * p;
            qb[e * SR + l]     = phi_fn(fmaf(rss[l],     s.x - mus[l] * dq,     cq));
            qb[e * SR + l + 1] = phi_fn(fmaf(rss[l + 1], s.y - mus[l + 1] * dq, cq));
        }
    }
    __syncthreads();

    // ---- attention: att[e][l] = (q . KV_col) / (q . Z + eps) ----
    int la = tid >> 1, half = tid & 1;
    float attv[32];
#pragma unroll
    for (int hq = 0; hq < 4; hq++) {
        int hh = half * 4 + hq;
        float q[8];
#pragma unroll
        for (int d = 0; d < 8; d++) q[d] = qb[(hh * 8 + d) * SR + la];
        float nrm = 1e-6f;
#pragma unroll
        for (int d = 0; d < 8; d++) nrm = fmaf(q[d], Zs[hh * 8 + d], nrm);
        float inv = 1.f / nrm;
#pragma unroll
        for (int j = 0; j < 8; j++) {
            float s = 0.f;
#pragma unroll
            for (int d = 0; d < 8; d++) s = fmaf(q[d], KVs[hh * 64 + d * 8 + j], s);
            attv[hq * 8 + j] = s * inv;
        }
    }
    __syncthreads();
#pragma unroll
    for (int i = 0; i < 32; i++)
        qb[(half * 32 + i) * SR + la] = attv[i];
    {   // wb <- WoT packed
        const float4* src = (const float4*)g_Wop;
        float4* dst = (float4*)wb;
#pragma unroll
        for (int i = 0; i < 8; i++) dst[tid + i * 256] = src[tid + i * 256];
    }
    __syncthreads();

    // ---- Wo GEMM + bias + residual -> g_y ----
    gemm_tile(qb + l0, wbase, acc);
#pragma unroll
    for (int i = 0; i < 4; i++) {
        int fo = e0 + i;
        float bb = bos[fo];
        const float* xr = xns + fo * SR + l0;
        float2 s0 = upk(acc[i][0]), s1 = upk(acc[i][1]);
        float2 s2 = upk(acc[i][2]), s3 = upk(acc[i][3]);
        float4 o0, o1;
        o0.x = s0.x + bb + xr[0]; o0.y = s0.y + bb + xr[1];
        o0.z = s1.x + bb + xr[2]; o0.w = s1.y + bb + xr[3];
        o1.x = s2.x + bb + xr[4]; o1.y = s2.y + bb + xr[5];
        o1.z = s3.x + bb + xr[6]; o1.w = s3.y + bb + xr[7];
        float* yb = g_y + ((size_t)(b * 64 + fo)) * Ln + l0b + l0;
        *(float4*)yb = o0;
        *(float4*)(yb + 4) = o1;
    }
}

// ---------------- kernel 4: temporal GEMM M[b,p,f] += sum_l Wlin[p,l]*y[b,f,l] ----------------
__global__ void __launch_bounds__(256, 2) k_gemm(const float* __restrict__ Wlin) {
    __shared__ float2 wls[96 * 33];
    __shared__ float2 ys[64 * 33];
    int b = blockIdx.y, tid = threadIdx.x;
    int lb0 = blockIdx.x * 256;
    int fg = tid & 15, pg = tid >> 4;

    ull acc[6][4];
#pragma unroll
    for (int i = 0; i < 6; i++)
#pragma unroll
        for (int k = 0; k < 4; k++) acc[i][k] = 0ULL;

    for (int s = 0; s < 4; s++) {
        int lb = lb0 + s * 64;
#pragma unroll
        for (int i = 0; i < 12; i++) {
            int idx = tid + i * 256;               // 3072 = 96*32
            int p = idx >> 5, j = idx & 31;
            wls[p * 33 + j] = *(const float2*)(Wlin + (size_t)p * Ln + lb + 2 * j);
        }
#pragma unroll
        for (int i = 0; i < 8; i++) {
            int idx = tid + i * 256;               // 2048 = 64*32
            int f = idx >> 5, j = idx & 31;
            ys[f * 33 + j] = *(const float2*)(g_y + ((size_t)(b * 64 + f)) * Ln + lb + 2 * j);
        }
        __syncthreads();
#pragma unroll 4
        for (int j = 0; j < 32; j++) {
            ull w[6], y[4];
#pragma unroll
            for (int i = 0; i < 6; i++) w[i] = ((const ull*)wls)[(pg + 16 * i) * 33 + j];
#pragma unroll
            for (int k = 0; k < 4; k++) y[k] = ((const ull*)ys)[(fg + 16 * k) * 33 + j];
#pragma unroll
            for (int i = 0; i < 6; i++)
#pragma unroll
                for (int k = 0; k < 4; k++) fma2(acc[i][k], w[i], y[k]);
        }
        __syncthreads();
    }
#pragma unroll
    for (int i = 0; i < 6; i++)
#pragma unroll
        for (int k = 0; k < 4; k++) {
            float2 t = upk(acc[i][k]);
            atomicAdd(&g_M[(b * 96 + pg + 16 * i) * 64 + fg + 16 * k], t.x + t.y);
        }
}

// ---------------- kernel 5: denorm + projector ----------------
__global__ void k_epi(const float* __restrict__ gamma, const float* __restrict__ beta,
                      const float* __restrict__ blin, const float* __restrict__ Wp,
                      const float* __restrict__ bp, float* __restrict__ out) {
    int b = blockIdx.x, p = threadIdx.x;
    float bl = blin[p];
    float s = bp[0];
#pragma unroll
    for (int f = 0; f < 64; f++) {
        float y = g_M[(b * 96 + p) * 64 + f] + bl;
        y = (y - beta[f]) / gamma[f];
        y = fmaf(y, g_stdp[b * 64 + f], g_mean[b * 64 + f]);
        s = fmaf(y, Wp[f], s);
    }
    out[b * 96 + p] = s;
}

// ---------------- launch ----------------
extern "C" void kernel_launch(void* const* d_in, const int* in_sizes, int n_in,
                              void* d_out, int out_size) {
    (void)in_sizes; (void)n_in; (void)out_size;
    const float* x     = (const float*)d_in[0];
    const float* gamma = (const float*)d_in[1];
    const float* beta  = (const float*)d_in[2];
    const float* lnw   = (const float*)d_in[3];
    const float* lnb   = (const float*)d_in[4];
    const float* Wq    = (const float*)d_in[5];
    const float* bq    = (const float*)d_in[6];
    const float* Wk    = (const float*)d_in[7];
    const float* bk    = (const float*)d_in[8];
    const float* Wv    = (const float*)d_in[9];
    const float* bv    = (const float*)d_in[10];
    const float* Wo    = (const float*)d_in[11];
    const float* bo    = (const float*)d_in[12];
    const float* Wlin  = (const float*)d_in[13];
    const float* blin  = (const float*)d_in[14];
    const float* Wp    = (const float*)d_in[15];
    const float* bp    = (const float*)d_in[16];
    float* out = (float*)d_out;

    const int SMB = (2 * 64 * SR + 8192) * 4;   // 100352 bytes dynamic shared
    cudaFuncSetAttribute(k_kv, cudaFuncAttributeMaxDynamicSharedMemorySize, SMB);
    cudaFuncSetAttribute(k_qo, cudaFuncAttributeMaxDynamicSharedMemorySize, SMB);

    k_zero<<<768, 256>>>();
    k_prep<<<1, 256>>>(lnw, lnb, Wq, bq, Wk, bk, Wv, bv, Wo);
    k_stats<<<Bn * Fn, 256>>>(x);
    k_kv<<<dim3(Ln / 128, Bn), 256, SMB>>>(x, gamma, beta);
    k_qo<<<dim3(Ln / 128, Bn), 256, SMB>>>(x, gamma, beta, bo);
    k_gemm<<<dim3(Ln / 256, Bn), 256>>>(Wlin);
    k_epi<<<Bn, Pn>>>(gamma, beta, blin, Wp, bp, out);
}

// round 3
// speedup vs baseline: 1.5957x; 1.3539x over previous
#include <cuda_runtime.h>
#include <cstdint>

#define Bn 32
#define Fn 64
#define Ln 8192
#define Pn 96
#define SR 132    // xn/q/v tile row stride (floats)
#define SRY 130   // y tile row stride (floats) -- conflict-free for fg-strided ull reads
#define SRW 132   // Wlin tile row stride

typedef unsigned long long ull;

// ---------------- scratch (device globals) ----------------
__device__ float g_mean[Bn * Fn];
__device__ float g_istd[Bn * Fn];
__device__ float g_stdp[Bn * Fn];
__device__ float g_KV[Bn * 512];
__device__ float g_Z[Bn * 64];
__device__ float g_M[Bn * Pn * Fn];
// pre-folded, duplicated (f32x2) weights: layout [k(=input dim)][e(=output dim)]
__device__ float2 g_Wqp[4096], g_Wkp[4096], g_Wvp[4096], g_Wop[4096];
__device__ float g_dq[64], g_cq[64], g_dk[64], g_ck[64], g_dv[64], g_cv[64];

// ---------------- helpers ----------------
__device__ __forceinline__ void fma2(ull& d, ull a, ull b) {
    asm("fma.rn.f32x2 %0, %1, %2, %0;" : "+l"(d) : "l"(a), "l"(b));
}
__device__ __forceinline__ float2 upk(ull v) {
    float2 r;
    asm("mov.b64 {%0, %1}, %2;" : "=f"(r.x), "=f"(r.y) : "l"(v));
    return r;
}
__device__ __forceinline__ ull pk2(float a, float b) {
    ull r;
    asm("mov.b64 %0, {%1, %2};" : "=l"(r) : "f"(a), "f"(b));
    return r;
}
__device__ __forceinline__ float phi_fn(float v) {
    return v > 0.f ? v + 1.f : __expf(v);   // elu(x)+1
}

// 64-deep GEMM micro-tile: 4 outputs (e) x 4 l-pairs at l = lg*2 + 32*p.
// hb = tile_base + lg*2 ; wbase = weight_ull_base + e0. Conflict-free by construction.
__device__ __forceinline__ void gemm_tile(const float* __restrict__ hb,
                                          const ull* __restrict__ wbase,
                                          ull acc[4][4]) {
#pragma unroll
    for (int i = 0; i < 4; i++) { acc[i][0] = acc[i][1] = acc[i][2] = acc[i][3] = 0ULL; }
#pragma unroll 8
    for (int k = 0; k < 64; k++) {
        ull h0 = *(const ull*)(hb + k * SR);
        ull h1 = *(const ull*)(hb + k * SR + 32);
        ull h2 = *(const ull*)(hb + k * SR + 64);
        ull h3 = *(const ull*)(hb + k * SR + 96);
        ulonglong2 w01 = *(const ulonglong2*)(wbase + k * 64);
        ulonglong2 w23 = *(const ulonglong2*)(wbase + k * 64 + 2);
        fma2(acc[0][0], w01.x, h0); fma2(acc[0][1], w01.x, h1);
        fma2(acc[0][2], w01.x, h2); fma2(acc[0][3], w01.x, h3);
        fma2(acc[1][0], w01.y, h0); fma2(acc[1][1], w01.y, h1);
        fma2(acc[1][2], w01.y, h2); fma2(acc[1][3], w01.y, h3);
        fma2(acc[2][0], w23.x, h0); fma2(acc[2][1], w23.x, h1);
        fma2(acc[2][2], w23.x, h2); fma2(acc[2][3], w23.x, h3);
        fma2(acc[3][0], w23.y, h0); fma2(acc[3][1], w23.y, h1);
        fma2(acc[3][2], w23.y, h2); fma2(acc[3][3], w23.y, h3);
    }
}

// ---------------- kernel 0: zero accumulators ----------------
__global__ void k_zero() {
    int i = blockIdx.x * blockDim.x + threadIdx.x;
    if (i < Bn * 512)      g_KV[i] = 0.f;
    if (i < Bn * 64)       g_Z[i]  = 0.f;
    if (i < Bn * Pn * Fn)  g_M[i]  = 0.f;
}

// ---------------- prep: fold LN into weights, duplicate pairs ----------------
__global__ void __launch_bounds__(256) k_prep(
    const float* __restrict__ lnw, const float* __restrict__ lnb,
    const float* __restrict__ Wq, const float* __restrict__ bq,
    const float* __restrict__ Wk, const float* __restrict__ bk,
    const float* __restrict__ Wv, const float* __restrict__ bv,
    const float* __restrict__ Wo)
{
    int tid = threadIdx.x;
#pragma unroll
    for (int i = 0; i < 16; i++) {
        int idx = tid + i * 256;          // idx = f*64 + e
        int f = idx >> 6, e = idx & 63;
        float lw = lnw[f];
        float wq = Wq[e * 64 + f] * lw;  g_Wqp[idx] = make_float2(wq, wq);
        float wk = Wk[e * 64 + f] * lw;  g_Wkp[idx] = make_float2(wk, wk);
        float wv = Wv[e * 64 + f] * lw;  g_Wvp[idx] = make_float2(wv, wv);
        float wo = Wo[e * 64 + f];       g_Wop[idx] = make_float2(wo, wo);  // [k=e_att][fo]
    }
    if (tid < 64) {
        int e = tid;
        float dq = 0.f, cq = 0.f, dk = 0.f, ck = 0.f, dv = 0.f, cv = 0.f;
        for (int f = 0; f < 64; f++) {
            float lw = lnw[f], lb2 = lnb[f];
            float wq = Wq[e * 64 + f], wk = Wk[e * 64 + f], wv = Wv[e * 64 + f];
            dq += wq * lw;  cq = fmaf(lb2, wq, cq);
            dk += wk * lw;  ck = fmaf(lb2, wk, ck);
            dv += wv * lw;  cv = fmaf(lb2, wv, cv);
        }
        g_dq[e] = dq; g_cq[e] = cq + bq[e];
        g_dk[e] = dk; g_ck[e] = ck + bk[e];
        g_dv[e] = dv; g_cv[e] = cv + bv[e];
    }
}

// ---------------- kernel 1: RevIN stats per (b,f) ----------------
__global__ void __launch_bounds__(256) k_stats(const float* __restrict__ x) {
    int bf = blockIdx.x;
    const float4* p = (const float4*)(x + (size_t)bf * Ln);
    float s1 = 0.f, s2 = 0.f;
    for (int i = threadIdx.x; i < Ln / 4; i += 256) {
        float4 v = p[i];
        s1 += (v.x + v.y) + (v.z + v.w);
        s2 = fmaf(v.x, v.x, s2); s2 = fmaf(v.y, v.y, s2);
        s2 = fmaf(v.z, v.z, s2); s2 = fmaf(v.w, v.w, s2);
    }
    __shared__ float r1[256], r2[256];
    r1[threadIdx.x] = s1; r2[threadIdx.x] = s2;
    __syncthreads();
    for (int s = 128; s > 0; s >>= 1) {
        if (threadIdx.x < s) {
            r1[threadIdx.x] += r1[threadIdx.x + s];
            r2[threadIdx.x] += r2[threadIdx.x + s];
        }
        __syncthreads();
    }
    if (threadIdx.x == 0) {
        float S1 = r1[0], S2 = r2[0];
        float mean = S1 / (float)Ln;
        float var = (S2 - S1 * mean) / (float)(Ln - 1);
        var = fmaxf(var, 0.f);
        float stdp = sqrtf(var) + 1e-5f;
        g_mean[bf] = mean; g_stdp[bf] = stdp; g_istd[bf] = 1.f / stdp;
    }
}

// ---------------- kernel 2: K/V projections + KV,Z ----------------
__global__ void __launch_bounds__(256, 2) k_kv(
    const float* __restrict__ x, const float* __restrict__ gamma, const float* __restrict__ beta)
{
    extern __shared__ float sm[];
    float*  xns = sm;                          // 64*SR; later holds phi(K)
    float*  vb  = sm + 64 * SR;                // 64*SR
    float2* wb  = (float2*)(sm + 2 * 64 * SR); // 4096 float2
    __shared__ float mus[128], rss[128], As[64], Cs[64];
    __shared__ float dks[64], cks[64], dvs[64], cvs[64];

    int b = blockIdx.y, tid = threadIdx.x;
    int l0b = blockIdx.x * 128;

    if (tid < 64) {
        float a = gamma[tid] * g_istd[b * 64 + tid];
        As[tid] = a;
        Cs[tid] = beta[tid] - g_mean[b * 64 + tid] * a;
        dks[tid] = g_dk[tid]; cks[tid] = g_ck[tid];
        dvs[tid] = g_dv[tid]; cvs[tid] = g_cv[tid];
    }
    {   // wb <- Wv packed
        const float4* src = (const float4*)g_Wvp;
        float4* dst = (float4*)wb;
#pragma unroll
        for (int i = 0; i < 8; i++) dst[tid + i * 256] = src[tid + i * 256];
    }
    __syncthreads();
#pragma unroll
    for (int i = 0; i < 8; i++) {
        int idx = tid + i * 256;
        int f = idx >> 5, c = idx & 31;
        float4 v = *(const float4*)(x + ((size_t)(b * 64 + f)) * Ln + l0b + c * 4);
        float a = As[f], c0 = Cs[f];
        v.x = fmaf(v.x, a, c0); v.y = fmaf(v.y, a, c0);
        v.z = fmaf(v.z, a, c0); v.w = fmaf(v.w, a, c0);
        *(float4*)(xns + f * SR + c * 4) = v;
    }
    __syncthreads();
    if (tid < 128) {
        float s1 = 0.f, s2 = 0.f;
#pragma unroll
        for (int f = 0; f < 64; f++) { float t = xns[f * SR + tid]; s1 += t; s2 = fmaf(t, t, s2); }
        float mu = s1 * (1.f / 64.f);
        mus[tid] = mu;
        rss[tid] = rsqrtf(fmaf(-mu, mu, s2 * (1.f / 64.f)) + 1e-5f);
    }
    __syncthreads();

    int lg = tid & 15, eg = tid >> 4;
    int e0 = eg * 4;
    const float* hb = xns + lg * 2;
    const ull* wbase = (const ull*)wb + e0;
    ull acc[4][4];

    // ---- V GEMM ----
    gemm_tile(hb, wbase, acc);
#pragma unroll
    for (int i = 0; i < 4; i++) {
        int e = e0 + i; float dv = dvs[e], cv = cvs[e];
#pragma unroll
        for (int p = 0; p < 4; p++) {
            float2 s = upk(acc[i][p]);
            int l = lg * 2 + 32 * p;
            *(ull*)(vb + e * SR + l) = pk2(
                fmaf(rss[l],     s.x - mus[l] * dv,     cv),
                fmaf(rss[l + 1], s.y - mus[l + 1] * dv, cv));
        }
    }
    __syncthreads();
    {   // wb <- Wk packed
        const float4* src = (const float4*)g_Wkp;
        float4* dst = (float4*)wb;
#pragma unroll
        for (int i = 0; i < 8; i++) dst[tid + i * 256] = src[tid + i * 256];
    }
    __syncthreads();

    // ---- K GEMM (phi into regs, then overwrite xns) ----
    gemm_tile(hb, wbase, acc);
    ull kreg[4][4];
#pragma unroll
    for (int i = 0; i < 4; i++) {
        int e = e0 + i; float dk = dks[e], ck = cks[e];
#pragma unroll
        for (int p = 0; p < 4; p++) {
            float2 s = upk(acc[i][p]);
            int l = lg * 2 + 32 * p;
            kreg[i][p] = pk2(
                phi_fn(fmaf(rss[l],     s.x - mus[l] * dk,     ck)),
                phi_fn(fmaf(rss[l + 1], s.y - mus[l + 1] * dk, ck)));
        }
    }
    __syncthreads();
#pragma unroll
    for (int i = 0; i < 4; i++)
#pragma unroll
        for (int p = 0; p < 4; p++)
            *(ull*)(xns + (e0 + i) * SR + lg * 2 + 32 * p) = kreg[i][p];
    __syncthreads();

    // ---- KV / Z accumulation ----
    if (tid < 128) {
        int hh = tid >> 4;
        int sub = tid & 15;
        int d0 = (sub >> 2) << 1;
        int e2 = (sub & 3) << 1;
        const float* kr0 = xns + (hh * 8 + d0) * SR;
        const float* kr1 = kr0 + SR;
        const float* vr0 = vb + (hh * 8 + e2) * SR;
        const float* vr1 = vr0 + SR;
        ull a00 = 0, a01 = 0, a10 = 0, a11 = 0;
#pragma unroll 4
        for (int j = 0; j < 128; j += 4) {
            ulonglong2 kk0 = *(const ulonglong2*)(kr0 + j);
            ulonglong2 kk1 = *(const ulonglong2*)(kr1 + j);
            ulonglong2 vv0 = *(const ulonglong2*)(vr0 + j);
            ulonglong2 vv1 = *(const ulonglong2*)(vr1 + j);
            fma2(a00, kk0.x, vv0.x); fma2(a00, kk0.y, vv0.y);
            fma2(a01, kk0.x, vv1.x); fma2(a01, kk0.y, vv1.y);
            fma2(a10, kk1.x, vv0.x); fma2(a10, kk1.y, vv0.y);
            fma2(a11, kk1.x, vv1.x); fma2(a11, kk1.y, vv1.y);
        }
        float* kvb = &g_KV[(b * 8 + hh) * 64];
        float2 t;
        t = upk(a00); atomicAdd(kvb + d0 * 8 + e2,           t.x + t.y);
        t = upk(a01); atomicAdd(kvb + d0 * 8 + e2 + 1,       t.x + t.y);
        t = upk(a10); atomicAdd(kvb + (d0 + 1) * 8 + e2,     t.x + t.y);
        t = upk(a11); atomicAdd(kvb + (d0 + 1) * 8 + e2 + 1, t.x + t.y);
    } else if (tid < 192) {
        int r = tid - 128;
        const float* kr = xns + r * SR;
        float s = 0.f;
#pragma unroll
        for (int j = 0; j < 128; j += 4) {
            float4 v = *(const float4*)(kr + j);
            s += (v.x + v.y) + (v.z + v.w);
        }
        atomicAdd(&g_Z[b * 64 + r], s);
    }
}

// ---------------- kernel 3: Q, attention, Wo+residual, fused temporal GEMM ----------------
__global__ void __launch_bounds__(256, 2) k_qo(
    const float* __restrict__ x, const float* __restrict__ gamma, const float* __restrict__ beta,
    const float* __restrict__ bo, const float* __restrict__ Wlin)
{
    extern __shared__ float sm[];
    float*  xns = sm;                          // xn tile; later y tile (stride SRY)
    float*  qb  = sm + 64 * SR;                // q/att tile; later Wlin slab (spans qb..wb)
    float2* wb  = (float2*)(sm + 2 * 64 * SR);
    float*  wls = qb;                          // 96*SRW floats = 12672 <= 16640 available
    __shared__ float mus[128], rss[128], As[64], Cs[64], dqs[64], cqs[64], bos[64];
    __shared__ float KVs[512], Zs[64];

    int b = blockIdx.y, tid = threadIdx.x;
    int l0b = blockIdx.x * 128;

    if (tid < 64) {
        float a = gamma[tid] * g_istd[b * 64 + tid];
        As[tid] = a;
        Cs[tid] = beta[tid] - g_mean[b * 64 + tid] * a;
        dqs[tid] = g_dq[tid]; cqs[tid] = g_cq[tid];
        bos[tid] = bo[tid];
        Zs[tid] = g_Z[b * 64 + tid];
    }
    KVs[tid] = g_KV[b * 512 + tid];
    KVs[tid + 256] = g_KV[b * 512 + 256 + tid];
    {   // wb <- Wq packed
        const float4* src = (const float4*)g_Wqp;
        float4* dst = (float4*)wb;
#pragma unroll
        for (int i = 0; i < 8; i++) dst[tid + i * 256] = src[tid + i * 256];
    }
    __syncthreads();
#pragma unroll
    for (int i = 0; i < 8; i++) {
        int idx = tid + i * 256;
        int f = idx >> 5, c = idx & 31;
        float4 v = *(const float4*)(x + ((size_t)(b * 64 + f)) * Ln + l0b + c * 4);
        float a = As[f], c0 = Cs[f];
        v.x = fmaf(v.x, a, c0); v.y = fmaf(v.y, a, c0);
        v.z = fmaf(v.z, a, c0); v.w = fmaf(v.w, a, c0);
        *(float4*)(xns + f * SR + c * 4) = v;
    }
    __syncthreads();
    if (tid < 128) {
        float s1 = 0.f, s2 = 0.f;
#pragma unroll
        for (int f = 0; f < 64; f++) { float t = xns[f * SR + tid]; s1 += t; s2 = fmaf(t, t, s2); }
        float mu = s1 * (1.f / 64.f);
        mus[tid] = mu;
        rss[tid] = rsqrtf(fmaf(-mu, mu, s2 * (1.f / 64.f)) + 1e-5f);
    }
    __syncthreads();

    int lg = tid & 15, eg = tid >> 4;
    int e0 = eg * 4;
    const ull* wbase = (const ull*)wb + e0;
    ull acc[4][4];

    // ---- Q GEMM -> phi -> qb ----
    gemm_tile(xns + lg * 2, wbase, acc);
#pragma unroll
    for (int i = 0; i < 4; i++) {
        int e = e0 + i; float dq = dqs[e], cq = cqs[e];
#pragma unroll
        for (int p = 0; p < 4; p++) {
            float2 s = upk(acc[i][p]);
            int l = lg * 2 + 32 * p;
            *(ull*)(qb + e * SR + l) = pk2(
                phi_fn(fmaf(rss[l],     s.x - mus[l] * dq,     cq)),
                phi_fn(fmaf(rss[l + 1], s.y - mus[l + 1] * dq, cq)));
        }
    }
    __syncthreads();

    // ---- attention per column ----
    int la = tid >> 1, half = tid & 1;
    float attv[32];
#pragma unroll
    for (int hq = 0; hq < 4; hq++) {
        int hh = half * 4 + hq;
        float q[8];
#pragma unroll
        for (int d = 0; d < 8; d++) q[d] = qb[(hh * 8 + d) * SR + la];
        float nrm = 1e-6f;
#pragma unroll
        for (int d = 0; d < 8; d++) nrm = fmaf(q[d], Zs[hh * 8 + d], nrm);
        float inv = 1.f / nrm;
#pragma unroll
        for (int j = 0; j < 8; j++) {
            float s = 0.f;
#pragma unroll
            for (int d = 0; d < 8; d++) s = fmaf(q[d], KVs[hh * 64 + d * 8 + j], s);
            attv[hq * 8 + j] = s * inv;
        }
    }
    __syncthreads();
#pragma unroll
    for (int i = 0; i < 32; i++)
        qb[(half * 32 + i) * SR + la] = attv[i];
    {   // wb <- WoT packed
        const float4* src = (const float4*)g_Wop;
        float4* dst = (float4*)wb;
#pragma unroll
        for (int i = 0; i < 8; i++) dst[tid + i * 256] = src[tid + i * 256];
    }
    __syncthreads();

    // ---- Wo GEMM + bias + residual -> y (registers) ----
    gemm_tile(qb + lg * 2, (const ull*)wb + e0, acc);
    ull yo[4][4];
#pragma unroll
    for (int i = 0; i < 4; i++) {
        int fo = e0 + i;
        float bb = bos[fo];
#pragma unroll
        for (int p = 0; p < 4; p++) {
            int l = lg * 2 + 32 * p;
            float2 s = upk(acc[i][p]);
            float2 r = upk(*(const ull*)(xns + fo * SR + l));
            yo[i][p] = pk2(s.x + bb + r.x, s.y + bb + r.y);
        }
    }
    __syncthreads();   // everyone done reading xns / qb / wb

    // ---- stage y into xns (stride SRY) and Wlin slab into qb..wb ----
#pragma unroll
    for (int i = 0; i < 4; i++)
#pragma unroll
        for (int p = 0; p < 4; p++)
            *(ull*)(xns + (e0 + i) * SRY + lg * 2 + 32 * p) = yo[i][p];
#pragma unroll
    for (int i = 0; i < 12; i++) {
        int idx = tid + i * 256;               // 3072 = 96 rows x 32 float4
        int p = idx >> 5, c4 = idx & 31;
        float4 v = *(const float4*)(Wlin + (size_t)p * Ln + l0b + c4 * 4);
        *(float4*)(wls + p * SRW + c4 * 4) = v;
    }
    __syncthreads();

    // ---- fused temporal GEMM: M[b,p,f] += sum_l Wlin[p,l] * y[f,l] ----
    int fg = tid & 15, pg = tid >> 4;
    const ull* yb  = (const ull*)xns;   // row stride SRY/2 = 65 ulls
    const ull* wsb = (const ull*)wls;   // row stride SRW/2 = 66 ulls
    ull acc2[6][4];
#pragma unroll
    for (int i = 0; i < 6; i++)
#pragma unroll
        for (int k = 0; k < 4; k++) acc2[i][k] = 0ULL;
#pragma unroll 4
    for (int j = 0; j < 64; j++) {
        ull yv[4], wv[6];
#pragma unroll
        for (int k = 0; k < 4; k++) yv[k] = yb[(fg + 16 * k) * 65 + j];
#pragma unroll
        for (int i = 0; i < 6; i++) wv[i] = wsb[(pg + 16 * i) * 66 + j];
#pragma unroll
        for (int i = 0; i < 6; i++)
#pragma unroll
            for (int k = 0; k < 4; k++) fma2(acc2[i][k], wv[i], yv[k]);
    }
#pragma unroll
    for (int i = 0; i < 6; i++)
#pragma unroll
        for (int k = 0; k < 4; k++) {
            float2 t = upk(acc2[i][k]);
            atomicAdd(&g_M[(b * 96 + pg + 16 * i) * 64 + fg + 16 * k], t.x + t.y);
        }
}

// ---------------- kernel 5: denorm + projector ----------------
__global__ void k_epi(const float* __restrict__ gamma, const float* __restrict__ beta,
                      const float* __restrict__ blin, const float* __restrict__ Wp,
                      const float* __restrict__ bp, float* __restrict__ out) {
    int b = blockIdx.x, p = threadIdx.x;
    float bl = blin[p];
    float s = bp[0];
#pragma unroll
    for (int f = 0; f < 64; f++) {
        float y = g_M[(b * 96 + p) * 64 + f] + bl;
        y = (y - beta[f]) / gamma[f];
        y = fmaf(y, g_stdp[b * 64 + f], g_mean[b * 64 + f]);
        s = fmaf(y, Wp[f], s);
    }
    out[b * 96 + p] = s;
}

// ---------------- launch ----------------
extern "C" void kernel_launch(void* const* d_in, const int* in_sizes, int n_in,
                              void* d_out, int out_size) {
    (void)in_sizes; (void)n_in; (void)out_size;
    const float* x     = (const float*)d_in[0];
    const float* gamma = (const float*)d_in[1];
    const float* beta  = (const float*)d_in[2];
    const float* lnw   = (const float*)d_in[3];
    const float* lnb   = (const float*)d_in[4];
    const float* Wq    = (const float*)d_in[5];
    const float* bq    = (const float*)d_in[6];
    const float* Wk    = (const float*)d_in[7];
    const float* bk    = (const float*)d_in[8];
    const float* Wv    = (const float*)d_in[9];
    const float* bv    = (const float*)d_in[10];
    const float* Wo    = (const float*)d_in[11];
    const float* bo    = (const float*)d_in[12];
    const float* Wlin  = (const float*)d_in[13];
    const float* blin  = (const float*)d_in[14];
    const float* Wp    = (const float*)d_in[15];
    const float* bp    = (const float*)d_in[16];
    float* out = (float*)d_out;

    const int SMB = (2 * 64 * SR + 8192) * 4;   // 100352 bytes dynamic shared
    cudaFuncSetAttribute(k_kv, cudaFuncAttributeMaxDynamicSharedMemorySize, SMB);
    cudaFuncSetAttribute(k_qo, cudaFuncAttributeMaxDynamicSharedMemorySize, SMB);

    k_zero<<<768, 256>>>();
    k_prep<<<1, 256>>>(lnw, lnb, Wq, bq, Wk, bk, Wv, bv, Wo);
    k_stats<<<Bn * Fn, 256>>>(x);
    k_kv<<<dim3(Ln / 128, Bn), 256, SMB>>>(x, gamma, beta);
    k_qo<<<dim3(Ln / 128, Bn), 256, SMB>>>(x, gamma, beta, bo, Wlin);
    k_epi<<<Bn, Pn>>>(gamma, beta, blin, Wp, bp, out);
}

// round 4
// speedup vs baseline: 1.6008x; 1.0032x over previous
#include <cuda_runtime.h>
#include <cstdint>

#define Bn 32
#define Fn 64
#define Ln 8192
#define Pn 96
#define SR 132    // xn/q/v tile row stride (floats)
#define SRY 130   // y tile row stride (floats) -- conflict-free for fg-strided ull reads
#define SRW 132   // Wlin tile row stride

typedef unsigned long long ull;

// ---------------- scratch (device globals) ----------------
__device__ float g_mean[Bn * Fn];
__device__ float g_istd[Bn * Fn];
__device__ float g_stdp[Bn * Fn];
__device__ float g_KV[Bn * 512];
__device__ float g_Z[Bn * 64];
__device__ float g_M[Bn * Pn * Fn];
// pre-folded, duplicated (f32x2) weights: layout [k(=input dim)][e(=output dim)]
__device__ float2 g_Wqp[4096], g_Wkp[4096], g_Wvp[4096], g_Wop[4096];
__device__ float g_dq[64], g_cq[64], g_dk[64], g_ck[64], g_dv[64], g_cv[64];

// ---------------- helpers ----------------
__device__ __forceinline__ void fma2(ull& d, ull a, ull b) {
    asm("fma.rn.f32x2 %0, %1, %2, %0;" : "+l"(d) : "l"(a), "l"(b));
}
__device__ __forceinline__ float2 upk(ull v) {
    float2 r;
    asm("mov.b64 {%0, %1}, %2;" : "=f"(r.x), "=f"(r.y) : "l"(v));
    return r;
}
__device__ __forceinline__ ull pk2(float a, float b) {
    ull r;
    asm("mov.b64 %0, {%1, %2};" : "=l"(r) : "f"(a), "f"(b));
    return r;
}
__device__ __forceinline__ float phi_fn(float v) {
    return v > 0.f ? v + 1.f : __expf(v);   // elu(x)+1
}

// 64-deep GEMM micro-tile: 4 outputs (e) x 4 l-pairs at l = lg*2 + 32*p.
// hb = tile_base + lg*2 ; wbase = weight_ull_base + e0. Conflict-free by construction.
__device__ __forceinline__ void gemm_tile(const float* __restrict__ hb,
                                          const ull* __restrict__ wbase,
                                          ull acc[4][4]) {
#pragma unroll
    for (int i = 0; i < 4; i++) { acc[i][0] = acc[i][1] = acc[i][2] = acc[i][3] = 0ULL; }
#pragma unroll 8
    for (int k = 0; k < 64; k++) {
        ull h0 = *(const ull*)(hb + k * SR);
        ull h1 = *(const ull*)(hb + k * SR + 32);
        ull h2 = *(const ull*)(hb + k * SR + 64);
        ull h3 = *(const ull*)(hb + k * SR + 96);
        ulonglong2 w01 = *(const ulonglong2*)(wbase + k * 64);
        ulonglong2 w23 = *(const ulonglong2*)(wbase + k * 64 + 2);
        fma2(acc[0][0], w01.x, h0); fma2(acc[0][1], w01.x, h1);
        fma2(acc[0][2], w01.x, h2); fma2(acc[0][3], w01.x, h3);
        fma2(acc[1][0], w01.y, h0); fma2(acc[1][1], w01.y, h1);
        fma2(acc[1][2], w01.y, h2); fma2(acc[1][3], w01.y, h3);
        fma2(acc[2][0], w23.x, h0); fma2(acc[2][1], w23.x, h1);
        fma2(acc[2][2], w23.x, h2); fma2(acc[2][3], w23.x, h3);
        fma2(acc[3][0], w23.y, h0); fma2(acc[3][1], w23.y, h1);
        fma2(acc[3][2], w23.y, h2); fma2(acc[3][3], w23.y, h3);
    }
}

// ---------------- kernel 0: zero accumulators ----------------
__global__ void k_zero() {
    int i = blockIdx.x * blockDim.x + threadIdx.x;
    if (i < Bn * 512)      g_KV[i] = 0.f;
    if (i < Bn * 64)       g_Z[i]  = 0.f;
    if (i < Bn * Pn * Fn)  g_M[i]  = 0.f;
}

// ---------------- prep: fold LN into weights, duplicate pairs ----------------
__global__ void __launch_bounds__(256) k_prep(
    const float* __restrict__ lnw, const float* __restrict__ lnb,
    const float* __restrict__ Wq, const float* __restrict__ bq,
    const float* __restrict__ Wk, const float* __restrict__ bk,
    const float* __restrict__ Wv, const float* __restrict__ bv,
    const float* __restrict__ Wo)
{
    int tid = threadIdx.x;
#pragma unroll
    for (int i = 0; i < 16; i++) {
        int idx = tid + i * 256;          // idx = f*64 + e
        int f = idx >> 6, e = idx & 63;
        float lw = lnw[f];
        float wq = Wq[e * 64 + f] * lw;  g_Wqp[idx] = make_float2(wq, wq);
        float wk = Wk[e * 64 + f] * lw;  g_Wkp[idx] = make_float2(wk, wk);
        float wv = Wv[e * 64 + f] * lw;  g_Wvp[idx] = make_float2(wv, wv);
        float wo = Wo[e * 64 + f];       g_Wop[idx] = make_float2(wo, wo);  // [k=e_att][fo]
    }
    if (tid < 64) {
        int e = tid;
        float dq = 0.f, cq = 0.f, dk = 0.f, ck = 0.f, dv = 0.f, cv = 0.f;
        for (int f = 0; f < 64; f++) {
            float lw = lnw[f], lb2 = lnb[f];
            float wq = Wq[e * 64 + f], wk = Wk[e * 64 + f], wv = Wv[e * 64 + f];
            dq += wq * lw;  cq = fmaf(lb2, wq, cq);
            dk += wk * lw;  ck = fmaf(lb2, wk, ck);
            dv += wv * lw;  cv = fmaf(lb2, wv, cv);
        }
        g_dq[e] = dq; g_cq[e] = cq + bq[e];
        g_dk[e] = dk; g_ck[e] = ck + bk[e];
        g_dv[e] = dv; g_cv[e] = cv + bv[e];
    }
}

// ---------------- kernel 1: RevIN stats per (b,f) ----------------
__global__ void __launch_bounds__(256) k_stats(const float* __restrict__ x) {
    int bf = blockIdx.x;
    const float4* p = (const float4*)(x + (size_t)bf * Ln);
    float s1 = 0.f, s2 = 0.f;
    for (int i = threadIdx.x; i < Ln / 4; i += 256) {
        float4 v = p[i];
        s1 += (v.x + v.y) + (v.z + v.w);
        s2 = fmaf(v.x, v.x, s2); s2 = fmaf(v.y, v.y, s2);
        s2 = fmaf(v.z, v.z, s2); s2 = fmaf(v.w, v.w, s2);
    }
    __shared__ float r1[256], r2[256];
    r1[threadIdx.x] = s1; r2[threadIdx.x] = s2;
    __syncthreads();
    for (int s = 128; s > 0; s >>= 1) {
        if (threadIdx.x < s) {
            r1[threadIdx.x] += r1[threadIdx.x + s];
            r2[threadIdx.x] += r2[threadIdx.x + s];
        }
        __syncthreads();
    }
    if (threadIdx.x == 0) {
        float S1 = r1[0], S2 = r2[0];
        float mean = S1 / (float)Ln;
        float var = (S2 - S1 * mean) / (float)(Ln - 1);
        var = fmaxf(var, 0.f);
        float stdp = sqrtf(var) + 1e-5f;
        g_mean[bf] = mean; g_stdp[bf] = stdp; g_istd[bf] = 1.f / stdp;
    }
}

// ---------------- kernel 2: K/V projections + KV,Z ----------------
__global__ void __launch_bounds__(256, 2) k_kv(
    const float* __restrict__ x, const float* __restrict__ gamma, const float* __restrict__ beta)
{
    extern __shared__ float sm[];
    float*  xns = sm;                          // 64*SR; later holds phi(K)
    float*  vb  = sm + 64 * SR;                // 64*SR
    float2* wb  = (float2*)(sm + 2 * 64 * SR); // 4096 float2
    __shared__ float mus[128], rss[128], As[64], Cs[64];
    __shared__ float dks[64], cks[64], dvs[64], cvs[64];

    int b = blockIdx.y, tid = threadIdx.x;
    int l0b = blockIdx.x * 128;

    if (tid < 64) {
        float a = gamma[tid] * g_istd[b * 64 + tid];
        As[tid] = a;
        Cs[tid] = beta[tid] - g_mean[b * 64 + tid] * a;
        dks[tid] = g_dk[tid]; cks[tid] = g_ck[tid];
        dvs[tid] = g_dv[tid]; cvs[tid] = g_cv[tid];
    }
    {   // wb <- Wv packed
        const float4* src = (const float4*)g_Wvp;
        float4* dst = (float4*)wb;
#pragma unroll
        for (int i = 0; i < 8; i++) dst[tid + i * 256] = src[tid + i * 256];
    }
    __syncthreads();
#pragma unroll
    for (int i = 0; i < 8; i++) {
        int idx = tid + i * 256;
        int f = idx >> 5, c = idx & 31;
        float4 v = *(const float4*)(x + ((size_t)(b * 64 + f)) * Ln + l0b + c * 4);
        float a = As[f], c0 = Cs[f];
        v.x = fmaf(v.x, a, c0); v.y = fmaf(v.y, a, c0);
        v.z = fmaf(v.z, a, c0); v.w = fmaf(v.w, a, c0);
        *(float4*)(xns + f * SR + c * 4) = v;
    }
    __syncthreads();
    if (tid < 128) {
        float s1 = 0.f, s2 = 0.f;
#pragma unroll
        for (int f = 0; f < 64; f++) { float t = xns[f * SR + tid]; s1 += t; s2 = fmaf(t, t, s2); }
        float mu = s1 * (1.f / 64.f);
        mus[tid] = mu;
        rss[tid] = rsqrtf(fmaf(-mu, mu, s2 * (1.f / 64.f)) + 1e-5f);
    }
    __syncthreads();

    int lg = tid & 15, eg = tid >> 4;
    int e0 = eg * 4;
    const float* hb = xns + lg * 2;
    const ull* wbase = (const ull*)wb + e0;
    ull acc[4][4];

    // ---- V GEMM ----
    gemm_tile(hb, wbase, acc);
#pragma unroll
    for (int i = 0; i < 4; i++) {
        int e = e0 + i; float dv = dvs[e], cv = cvs[e];
#pragma unroll
        for (int p = 0; p < 4; p++) {
            float2 s = upk(acc[i][p]);
            int l = lg * 2 + 32 * p;
            *(ull*)(vb + e * SR + l) = pk2(
                fmaf(rss[l],     s.x - mus[l] * dv,     cv),
                fmaf(rss[l + 1], s.y - mus[l + 1] * dv, cv));
        }
    }
    __syncthreads();
    {   // wb <- Wk packed
        const float4* src = (const float4*)g_Wkp;
        float4* dst = (float4*)wb;
#pragma unroll
        for (int i = 0; i < 8; i++) dst[tid + i * 256] = src[tid + i * 256];
    }
    __syncthreads();

    // ---- K GEMM (phi into regs, then overwrite xns) ----
    gemm_tile(hb, wbase, acc);
    ull kreg[4][4];
#pragma unroll
    for (int i = 0; i < 4; i++) {
        int e = e0 + i; float dk = dks[e], ck = cks[e];
#pragma unroll
        for (int p = 0; p < 4; p++) {
            float2 s = upk(acc[i][p]);
            int l = lg * 2 + 32 * p;
            kreg[i][p] = pk2(
                phi_fn(fmaf(rss[l],     s.x - mus[l] * dk,     ck)),
                phi_fn(fmaf(rss[l + 1], s.y - mus[l + 1] * dk, ck)));
        }
    }
    __syncthreads();
#pragma unroll
    for (int i = 0; i < 4; i++)
#pragma unroll
        for (int p = 0; p < 4; p++)
            *(ull*)(xns + (e0 + i) * SR + lg * 2 + 32 * p) = kreg[i][p];
    __syncthreads();

    // ---- KV / Z accumulation ----
    if (tid < 128) {
        int hh = tid >> 4;
        int sub = tid & 15;
        int d0 = (sub >> 2) << 1;
        int e2 = (sub & 3) << 1;
        const float* kr0 = xns + (hh * 8 + d0) * SR;
        const float* kr1 = kr0 + SR;
        const float* vr0 = vb + (hh * 8 + e2) * SR;
        const float* vr1 = vr0 + SR;
        ull a00 = 0, a01 = 0, a10 = 0, a11 = 0;
#pragma unroll 4
        for (int j = 0; j < 128; j += 4) {
            ulonglong2 kk0 = *(const ulonglong2*)(kr0 + j);
            ulonglong2 kk1 = *(const ulonglong2*)(kr1 + j);
            ulonglong2 vv0 = *(const ulonglong2*)(vr0 + j);
            ulonglong2 vv1 = *(const ulonglong2*)(vr1 + j);
            fma2(a00, kk0.x, vv0.x); fma2(a00, kk0.y, vv0.y);
            fma2(a01, kk0.x, vv1.x); fma2(a01, kk0.y, vv1.y);
            fma2(a10, kk1.x, vv0.x); fma2(a10, kk1.y, vv0.y);
            fma2(a11, kk1.x, vv1.x); fma2(a11, kk1.y, vv1.y);
        }
        float* kvb = &g_KV[(b * 8 + hh) * 64];
        float2 t;
        t = upk(a00); atomicAdd(kvb + d0 * 8 + e2,           t.x + t.y);
        t = upk(a01); atomicAdd(kvb + d0 * 8 + e2 + 1,       t.x + t.y);
        t = upk(a10); atomicAdd(kvb + (d0 + 1) * 8 + e2,     t.x + t.y);
        t = upk(a11); atomicAdd(kvb + (d0 + 1) * 8 + e2 + 1, t.x + t.y);
    } else if (tid < 192) {
        int r = tid - 128;
        const float* kr = xns + r * SR;
        float s = 0.f;
#pragma unroll
        for (int j = 0; j < 128; j += 4) {
            float4 v = *(const float4*)(kr + j);
            s += (v.x + v.y) + (v.z + v.w);
        }
        atomicAdd(&g_Z[b * 64 + r], s);
    }
}

// ---------------- kernel 3: Q, attention, Wo+residual, fused temporal GEMM ----------------
__global__ void __launch_bounds__(256, 2) k_qo(
    const float* __restrict__ x, const float* __restrict__ gamma, const float* __restrict__ beta,
    const float* __restrict__ bo, const float* __restrict__ Wlin)
{
    extern __shared__ float sm[];
    float*  xns = sm;                          // xn tile; later y tile (stride SRY)
    float*  qb  = sm + 64 * SR;                // q/att tile; later Wlin slab (spans qb..wb)
    float2* wb  = (float2*)(sm + 2 * 64 * SR);
    float*  wls = qb;                          // 96*SRW floats = 12672 <= 16640 available
    __shared__ float mus[128], rss[128], As[64], Cs[64], dqs[64], cqs[64], bos[64];
    __shared__ float KVs[512], Zs[64];

    int b = blockIdx.y, tid = threadIdx.x;
    int l0b = blockIdx.x * 128;

    if (tid < 64) {
        float a = gamma[tid] * g_istd[b * 64 + tid];
        As[tid] = a;
        Cs[tid] = beta[tid] - g_mean[b * 64 + tid] * a;
        dqs[tid] = g_dq[tid]; cqs[tid] = g_cq[tid];
        bos[tid] = bo[tid];
        Zs[tid] = g_Z[b * 64 + tid];
    }
    KVs[tid] = g_KV[b * 512 + tid];
    KVs[tid + 256] = g_KV[b * 512 + 256 + tid];
    {   // wb <- Wq packed
        const float4* src = (const float4*)g_Wqp;
        float4* dst = (float4*)wb;
#pragma unroll
        for (int i = 0; i < 8; i++) dst[tid + i * 256] = src[tid + i * 256];
    }
    __syncthreads();
#pragma unroll
    for (int i = 0; i < 8; i++) {
        int idx = tid + i * 256;
        int f = idx >> 5, c = idx & 31;
        float4 v = *(const float4*)(x + ((size_t)(b * 64 + f)) * Ln + l0b + c * 4);
        float a = As[f], c0 = Cs[f];
        v.x = fmaf(v.x, a, c0); v.y = fmaf(v.y, a, c0);
        v.z = fmaf(v.z, a, c0); v.w = fmaf(v.w, a, c0);
        *(float4*)(xns + f * SR + c * 4) = v;
    }
    __syncthreads();
    if (tid < 128) {
        float s1 = 0.f, s2 = 0.f;
#pragma unroll
        for (int f = 0; f < 64; f++) { float t = xns[f * SR + tid]; s1 += t; s2 = fmaf(t, t, s2); }
        float mu = s1 * (1.f / 64.f);
        mus[tid] = mu;
        rss[tid] = rsqrtf(fmaf(-mu, mu, s2 * (1.f / 64.f)) + 1e-5f);
    }
    __syncthreads();

    int lg = tid & 15, eg = tid >> 4;
    int e0 = eg * 4;
    const ull* wbase = (const ull*)wb + e0;
    ull acc[4][4];

    // ---- Q GEMM -> phi -> qb ----
    gemm_tile(xns + lg * 2, wbase, acc);
#pragma unroll
    for (int i = 0; i < 4; i++) {
        int e = e0 + i; float dq = dqs[e], cq = cqs[e];
#pragma unroll
        for (int p = 0; p < 4; p++) {
            float2 s = upk(acc[i][p]);
            int l = lg * 2 + 32 * p;
            *(ull*)(qb + e * SR + l) = pk2(
                phi_fn(fmaf(rss[l],     s.x - mus[l] * dq,     cq)),
                phi_fn(fmaf(rss[l + 1], s.y - mus[l + 1] * dq, cq)));
        }
    }
    __syncthreads();

    // ---- attention per column ----
    int la = tid >> 1, half = tid & 1;
    float attv[32];
#pragma unroll
    for (int hq = 0; hq < 4; hq++) {
        int hh = half * 4 + hq;
        float q[8];
#pragma unroll
        for (int d = 0; d < 8; d++) q[d] = qb[(hh * 8 + d) * SR + la];
        float nrm = 1e-6f;
#pragma unroll
        for (int d = 0; d < 8; d++) nrm = fmaf(q[d], Zs[hh * 8 + d], nrm);
        float inv = 1.f / nrm;
#pragma unroll
        for (int j = 0; j < 8; j++) {
            float s = 0.f;
#pragma unroll
            for (int d = 0; d < 8; d++) s = fmaf(q[d], KVs[hh * 64 + d * 8 + j], s);
            attv[hq * 8 + j] = s * inv;
        }
    }
    __syncthreads();
#pragma unroll
    for (int i = 0; i < 32; i++)
        qb[(half * 32 + i) * SR + la] = attv[i];
    {   // wb <- WoT packed
        const float4* src = (const float4*)g_Wop;
        float4* dst = (float4*)wb;
#pragma unroll
        for (int i = 0; i < 8; i++) dst[tid + i * 256] = src[tid + i * 256];
    }
    __syncthreads();

    // ---- Wo GEMM + bias + residual -> y (registers) ----
    gemm_tile(qb + lg * 2, (const ull*)wb + e0, acc);
    ull yo[4][4];
#pragma unroll
    for (int i = 0; i < 4; i++) {
        int fo = e0 + i;
        float bb = bos[fo];
#pragma unroll
        for (int p = 0; p < 4; p++) {
            int l = lg * 2 + 32 * p;
            float2 s = upk(acc[i][p]);
            float2 r = upk(*(const ull*)(xns + fo * SR + l));
            yo[i][p] = pk2(s.x + bb + r.x, s.y + bb + r.y);
        }
    }
    __syncthreads();   // everyone done reading xns / qb / wb

    // ---- stage y into xns (stride SRY) and Wlin slab into qb..wb ----
#pragma unroll
    for (int i = 0; i < 4; i++)
#pragma unroll
        for (int p = 0; p < 4; p++)
            *(ull*)(xns + (e0 + i) * SRY + lg * 2 + 32 * p) = yo[i][p];
#pragma unroll
    for (int i = 0; i < 12; i++) {
        int idx = tid + i * 256;               // 3072 = 96 rows x 32 float4
        int p = idx >> 5, c4 = idx & 31;
        float4 v = *(const float4*)(Wlin + (size_t)p * Ln + l0b + c4 * 4);
        *(float4*)(wls + p * SRW + c4 * 4) = v;
    }
    __syncthreads();

    // ---- fused temporal GEMM: M[b,p,f] += sum_l Wlin[p,l] * y[f,l] ----
    int fg = tid & 15, pg = tid >> 4;
    const ull* yb  = (const ull*)xns;   // row stride SRY/2 = 65 ulls
    const ull* wsb = (const ull*)wls;   // row stride SRW/2 = 66 ulls
    ull acc2[6][4];
#pragma unroll
    for (int i = 0; i < 6; i++)
#pragma unroll
        for (int k = 0; k < 4; k++) acc2[i][k] = 0ULL;
#pragma unroll 4
    for (int j = 0; j < 64; j++) {
        ull yv[4], wv[6];
#pragma unroll
        for (int k = 0; k < 4; k++) yv[k] = yb[(fg + 16 * k) * 65 + j];
#pragma unroll
        for (int i = 0; i < 6; i++) wv[i] = wsb[(pg + 16 * i) * 66 + j];
#pragma unroll
        for (int i = 0; i < 6; i++)
#pragma unroll
            for (int k = 0; k < 4; k++) fma2(acc2[i][k], wv[i], yv[k]);
    }
#pragma unroll
    for (int i = 0; i < 6; i++)
#pragma unroll
        for (int k = 0; k < 4; k++) {
            float2 t = upk(acc2[i][k]);
            atomicAdd(&g_M[(b * 96 + pg + 16 * i) * 64 + fg + 16 * k], t.x + t.y);
        }
}

// ---------------- kernel 5: denorm + projector ----------------
__global__ void k_epi(const float* __restrict__ gamma, const float* __restrict__ beta,
                      const float* __restrict__ blin, const float* __restrict__ Wp,
                      const float* __restrict__ bp, float* __restrict__ out) {
    int b = blockIdx.x, p = threadIdx.x;
    float bl = blin[p];
    float s = bp[0];
#pragma unroll
    for (int f = 0; f < 64; f++) {
        float y = g_M[(b * 96 + p) * 64 + f] + bl;
        y = (y - beta[f]) / gamma[f];
        y = fmaf(y, g_stdp[b * 64 + f], g_mean[b * 64 + f]);
        s = fmaf(y, Wp[f], s);
    }
    out[b * 96 + p] = s;
}

// ---------------- launch ----------------
extern "C" void kernel_launch(void* const* d_in, const int* in_sizes, int n_in,
                              void* d_out, int out_size) {
    (void)in_sizes; (void)n_in; (void)out_size;
    const float* x     = (const float*)d_in[0];
    const float* gamma = (const float*)d_in[1];
    const float* beta  = (const float*)d_in[2];
    const float* lnw   = (const float*)d_in[3];
    const float* lnb   = (const float*)d_in[4];
    const float* Wq    = (const float*)d_in[5];
    const float* bq    = (const float*)d_in[6];
    const float* Wk    = (const float*)d_in[7];
    const float* bk    = (const float*)d_in[8];
    const float* Wv    = (const float*)d_in[9];
    const float* bv    = (const float*)d_in[10];
    const float* Wo    = (const float*)d_in[11];
    const float* bo    = (const float*)d_in[12];
    const float* Wlin  = (const float*)d_in[13];
    const float* blin  = (const float*)d_in[14];
    const float* Wp    = (const float*)d_in[15];
    const float* bp    = (const float*)d_in[16];
    float* out = (float*)d_out;

    const int SMB = (2 * 64 * SR + 8192) * 4;   // 100352 bytes dynamic shared
    cudaFuncSetAttribute(k_kv, cudaFuncAttributeMaxDynamicSharedMemorySize, SMB);
    cudaFuncSetAttribute(k_qo, cudaFuncAttributeMaxDynamicSharedMemorySize, SMB);

    k_zero<<<768, 256>>>();
    k_prep<<<1, 256>>>(lnw, lnb, Wq, bq, Wk, bk, Wv, bv, Wo);
    k_stats<<<Bn * Fn, 256>>>(x);
    k_kv<<<dim3(Ln / 128, Bn), 256, SMB>>>(x, gamma, beta);
    k_qo<<<dim3(Ln / 128, Bn), 256, SMB>>>(x, gamma, beta, bo, Wlin);
    k_epi<<<Bn, Pn>>>(gamma, beta, blin, Wp, bp, out);
}